// round 12
// baseline (speedup 1.0000x reference)
#include <cuda_runtime.h>
#include <math.h>

#define BQ 300   // predictions (columns of LSA)
#define BT 50    // truths (rows of LSA)
#define NB 32    // batch
#define NTHREADS 320
#define KPL 10   // columns per lane (32*10 = 320 >= 300)
#define UMAX64 0xFFFFFFFFFFFFFFFFULL

// Fixed-point scale 2^40: f32 costs convert exactly; all solver arithmetic is
// exact int64. Costs biased by +4 (uniform shift, matching-invariant) so every
// cost/distance is nonnegative -> packable as unsigned (d<<9)|j keys.
#define FIXSCALE 1099511627776.0
#define CBIAS    (4LL << 40)

extern __shared__ long long cfix[];   // BT*BQ int64 biased costs (120000 B)

// Warp-wide min of packed (d<<9)|j keys: unsigned min IS argmin with
// lowest-j tie-break. 5-round butterfly; all lanes receive the result.
__device__ __forceinline__ unsigned long long warp_min64(unsigned long long p)
{
    #pragma unroll
    for (int off = 16; off > 0; off >>= 1) {
        unsigned long long o = __shfl_xor_sync(0xffffffffu, p, off);
        p = (o < p) ? o : p;
    }
    return p;
}

__global__ __launch_bounds__(NTHREADS, 1)
void hungarian_kernel(const float* __restrict__ pred,
                      const float* __restrict__ truth,
                      float* __restrict__ out)
{
    __shared__ float     st[BT * 4];
    __shared__ long long u_s[BT];     // row duals (fixed-point, biased space)
    __shared__ long long ss64[BQ];    // frozen shortest at selection
    __shared__ unsigned long long rmin[BT];  // packed row minima
    __shared__ short     path_s[BQ];
    __shared__ short     row4col[BQ];
    __shared__ short     col4row[BT];

    const int b   = blockIdx.x;
    const int tid = threadIdx.x;

    // Phase 0: stage truth boxes + init matching state
    for (int k = tid; k < BT * 4; k += NTHREADS) st[k] = truth[b * BT * 4 + k];
    for (int k = tid; k < BQ; k += NTHREADS) row4col[k] = -1;
    for (int k = tid; k < BT; k += NTHREADS) col4row[k] = -1;
    __syncthreads();

    // Phase 1: cost matrix, column-per-thread. Thread j owns pred box j:
    // derived geometry computed once; loop over 50 truths (uniform broadcasts).
    if (tid < BQ) {
        const int j = tid;
        const float pcx = pred[(b * BQ + j) * 4 + 0];
        const float pcy = pred[(b * BQ + j) * 4 + 1];
        const float pw  = pred[(b * BQ + j) * 4 + 2];
        const float ph  = pred[(b * BQ + j) * 4 + 3];
        const float px0 = pcx - 0.5f * pw, py0 = pcy - 0.5f * ph;
        const float px1 = pcx + 0.5f * pw, py1 = pcy + 0.5f * ph;
        const float parea = (px1 - px0) * (py1 - py0);

        for (int i = 0; i < BT; i++) {
            const float tcx = st[i*4+0], tcy = st[i*4+1];
            const float tw  = st[i*4+2], th  = st[i*4+3];
            float l1 = fabsf(pcx - tcx) + fabsf(pcy - tcy)
                     + fabsf(pw - tw)  + fabsf(ph - th);
            float tx0 = tcx - 0.5f * tw, ty0 = tcy - 0.5f * th;
            float tx1 = tcx + 0.5f * tw, ty1 = tcy + 0.5f * th;
            float tarea = (tx1 - tx0) * (ty1 - ty0);
            float ltx = fmaxf(px0, tx0), lty = fmaxf(py0, ty0);
            float rbx = fminf(px1, tx1), rby = fminf(py1, ty1);
            float wx = fmaxf(rbx - ltx, 0.f), wy = fmaxf(rby - lty, 0.f);
            float inter = wx * wy;
            float uni   = parea + tarea - inter;
            float iou   = inter / uni;
            float ex0 = fminf(px0, tx0), ey0 = fminf(py0, ty0);
            float ex1 = fmaxf(px1, tx1), ey1 = fmaxf(py1, ty1);
            float ew = fmaxf(ex1 - ex0, 0.f), eh = fmaxf(ey1 - ey0, 0.f);
            float ae   = ew * eh;
            float giou = iou - (ae - uni) / ae;
            float c    = 5.0f * l1 - 2.0f * giou;
            cfix[i * BQ + j] = __double2ll_rn((double)c * FIXSCALE) + CBIAS;
        }
    }
    __syncthreads();

    // Phase 1.5: packed per-row minima (warp w handles rows w, w+10, ...)
    {
        const int w = tid >> 5, ln = tid & 31;
        for (int i = w; i < BT; i += NTHREADS / 32) {
            unsigned long long bp = UMAX64;
            #pragma unroll
            for (int k = 0; k < KPL; k++) {
                const int j = ln + 32 * k;
                if (j < BQ) {
                    unsigned long long p =
                        (((unsigned long long)cfix[i * BQ + j]) << 9) | (unsigned)j;
                    if (p < bp) bp = p;
                }
            }
            bp = warp_min64(bp);
            if (ln == 0) rmin[i] = bp;
        }
    }
    __syncthreads();

    // Phase 2: single-warp exact JV solver.
    if (tid >= 32) return;
    const int lane = tid;

    // Greedy init: u_i = row min (feasible duals, tight matched edges).
    if (lane == 0) {
        for (int i = 0; i < BT; i++) {
            const unsigned long long p = rmin[i];
            u_s[i] = (long long)(p >> 9);
            const int j = (int)(p & 511u);
            if (row4col[j] < 0) { row4col[j] = (short)i; col4row[i] = (short)j; }
        }
    }
    __syncwarp();

    long long          vv64[KPL];     // column duals v (lane-resident)
    unsigned long long sdp[KPL];      // packed shortest distances (d<<9)|j
    unsigned valid = 0;
    #pragma unroll
    for (int k = 0; k < KPL; k++) {
        vv64[k] = 0;
        if (lane + 32 * k < BQ) valid |= (1u << k);
    }

    for (int cur = 0; cur < BT; cur++) {
        if (col4row[cur] >= 0) continue;   // assigned by greedy init

        unsigned avail = valid, sel = 0;
        #pragma unroll
        for (int k = 0; k < KPL; k++) sdp[k] = UMAX64;
        unsigned long long lbp = UMAX64;   // lane-local running packed min

        int       i = cur, sink = -1;
        long long mv = 0, u_i = u_s[cur];

        for (int guard = 0; guard <= BQ && sink < 0; guard++) {
            // Relax all available columns owned by this lane (int64 ALU only).
            const long long  s    = mv - u_i;
            const long long* crow = &cfix[i * BQ];
            #pragma unroll
            for (int k = 0; k < KPL; k++) {
                if (avail & (1u << k)) {
                    const int j = lane + 32 * k;
                    const long long d = s + (crow[j] - vv64[k]);
                    const unsigned long long dp =
                        (((unsigned long long)d) << 9) | (unsigned)j;
                    if (dp < sdp[k]) {
                        sdp[k] = dp;
                        path_s[j] = (short)i;
                        if (dp < lbp) lbp = dp;
                    }
                }
            }
            // One packed 64-bit warp min = exact argmin, lowest-j tie-break.
            const unsigned long long mp = warp_min64(lbp);
            const int mj = (int)(mp & 511u);
            mv = (long long)(mp >> 9);
            if (lane == (mj & 31)) {              // winner freezes its column
                const int kk = mj >> 5;
                sdp[kk] = UMAX64;
                avail &= ~(1u << kk);
                sel   |=  (1u << kk);
                ss64[mj] = mv;
                lbp = UMAX64;                      // rescan lane best
                #pragma unroll
                for (int k2 = 0; k2 < KPL; k2++)
                    if (sdp[k2] < lbp) lbp = sdp[k2];
            }
            const int r = row4col[mj];
            if (r < 0) sink = mj;
            else { i = r; u_i = u_s[i]; }
        }
        __syncwarp();

        // Dual updates (pre-augmentation; exact integer algebra)
        #pragma unroll
        for (int k = 0; k < KPL; k++) {
            if (sel & (1u << k)) {
                const int j = lane + 32 * k;
                const long long delta = mv - ss64[j];
                vv64[k] -= delta;                 // v[j] -= mv - shortest[j]
                const int r = row4col[j];         // pre-augment matching
                if (r >= 0) u_s[r] += delta;      // distinct r per lane/k
            }
        }
        if (lane == 0) u_s[cur] += mv;
        __syncwarp();

        // Augment along the path (lane 0)
        if (lane == 0) {
            int j = sink;
            while (j >= 0) {
                const int i2 = path_s[j];
                row4col[j] = (short)i2;
                const int tmp = col4row[i2];
                col4row[i2] = (short)j;
                j = tmp;
                if (i2 == cur) break;
            }
        }
        __syncwarp();
    }

    // Output (float32): pairs sorted by pred index; rank = #(assigned preds < mine)
    for (int t = lane; t < BT; t += 32) {
        const int my = col4row[t];
        int rank = 0;
        for (int t2 = 0; t2 < BT; t2++) rank += (col4row[t2] < my) ? 1 : 0;
        out[b * 2 * BT + rank]      = (float)my;
        out[b * 2 * BT + BT + rank] = (float)t;
    }
}

extern "C" void kernel_launch(void* const* d_in, const int* in_sizes, int n_in,
                              void* d_out, int out_size)
{
    // pred_boxes (32x300x4) is the LARGER buffer in either units/order.
    const float* pred;
    const float* truth;
    if (n_in >= 2 && in_sizes[1] > in_sizes[0]) {
        pred  = (const float*)d_in[1];
        truth = (const float*)d_in[0];
    } else {
        pred  = (const float*)d_in[0];
        truth = (const float*)d_in[1];
    }
    (void)out_size;

    const int dyn_smem = BT * BQ * (int)sizeof(long long);   // 120000 B
    cudaFuncSetAttribute(hungarian_kernel,
                         cudaFuncAttributeMaxDynamicSharedMemorySize, dyn_smem);
    hungarian_kernel<<<NB, NTHREADS, dyn_smem>>>(pred, truth, (float*)d_out);
}